// round 4
// baseline (speedup 1.0000x reference)
#include <cuda_runtime.h>

#define N_NODES 10000
#define N_EDGES 160000
#define F0      50
#define KP1     112      // padded K for layer-1 GEMM ([agg_x | x] = 100 -> 112)
#define HID     512
#define F2      121
#define N2      256      // padded N for layer-2 GEMM ([q | r] = 242 -> 256)

// ---------------- scratch (device globals; no allocations allowed) -----------
__device__ int   g_is64;
__device__ int   g_deg[N_NODES];
__device__ int   g_rowstart[N_NODES];
__device__ int   g_cursor[N_NODES];
__device__ float g_invdeg[N_NODES];
__device__ int   g_esrc[N_EDGES];
__device__ float g_xa[N_NODES * KP1];       // [mean_agg(x) | x | 0pad]
__device__ float g_wc1[KP1 * HID];          // [W1_l ; W1_r ; 0pad]
__device__ float g_h[N_NODES * HID];        // relu(layer1)
__device__ float g_wc2[HID * N2];           // [W2_l | W2_r | 0pad]
__device__ float g_qr[N_NODES * N2];        // [q | r | pad]

// ---------------- edge-index dtype detection ---------------------------------
// int64 data with values in [0, 2^31): every odd int32 word (high half) is 0.
// Real int32 edge data: odd positions are edge values, overwhelmingly nonzero.
__global__ void detect_kernel(const int* __restrict__ ei32) {
    if (threadIdx.x == 0 && blockIdx.x == 0) {
        int odd_nonzero = 0;
        for (int i = 1; i < 4096; i += 2) odd_nonzero |= (ei32[i] != 0);
        g_is64 = odd_nonzero ? 0 : 1;
    }
}

__device__ __forceinline__ int load_idx(const void* ei, int pos) {
    int v = g_is64 ? (int)((const long long*)ei)[pos]
                   : ((const int*)ei)[pos];
    // defensive clamp: a wrong dtype guess should fail rel_err, not segfault
    return min(max(v, 0), N_NODES - 1);
}

// ---------------- CSR build --------------------------------------------------
__global__ void zero_deg_kernel() {
    int i = blockIdx.x * blockDim.x + threadIdx.x;
    if (i < N_NODES) g_deg[i] = 0;
}

__global__ void count_kernel(const void* __restrict__ ei) {
    int e = blockIdx.x * blockDim.x + threadIdx.x;
    if (e < N_EDGES) atomicAdd(&g_deg[load_idx(ei, N_EDGES + e)], 1);
}

__global__ void scan_kernel() {
    // exclusive prefix sum of g_deg over 10000 nodes; single block of 1024.
    const int CH = 10;  // 1024*10 >= 10000
    __shared__ int s[1024];
    int t = threadIdx.x;
    int base = t * CH;
    int local[CH];
    int sum = 0;
#pragma unroll
    for (int i = 0; i < CH; i++) {
        int idx = base + i;
        int v = (idx < N_NODES) ? g_deg[idx] : 0;
        local[i] = v;
        sum += v;
    }
    s[t] = sum;
    __syncthreads();
    for (int off = 1; off < 1024; off <<= 1) {
        int v = (t >= off) ? s[t - off] : 0;
        __syncthreads();
        s[t] += v;
        __syncthreads();
    }
    int excl = s[t] - sum;
#pragma unroll
    for (int i = 0; i < CH; i++) {
        int idx = base + i;
        if (idx < N_NODES) {
            g_rowstart[idx] = excl;
            g_cursor[idx]   = excl;
            int d = local[i];
            g_invdeg[idx] = 1.0f / (float)(d > 1 ? d : 1);
            excl += d;
        }
    }
}

__global__ void bucket_kernel(const void* __restrict__ ei) {
    int e = blockIdx.x * blockDim.x + threadIdx.x;
    if (e < N_EDGES) {
        int dst = load_idx(ei, N_EDGES + e);
        int pos = atomicAdd(&g_cursor[dst], 1);
        pos = min(max(pos, 0), N_EDGES - 1);
        g_esrc[pos] = load_idx(ei, e);
    }
}

// ---------------- weight concat ----------------------------------------------
__global__ void wc1_kernel(const float* __restrict__ W1l, const float* __restrict__ W1r) {
    int idx = blockIdx.x * blockDim.x + threadIdx.x;
    if (idx >= KP1 * HID) return;
    int k = idx / HID, j = idx % HID;
    float v = 0.0f;
    if (k < F0)            v = W1l[k * HID + j];
    else if (k < 2 * F0)   v = W1r[(k - F0) * HID + j];
    g_wc1[idx] = v;
}

__global__ void wc2_kernel(const float* __restrict__ W2l, const float* __restrict__ W2r) {
    int idx = blockIdx.x * blockDim.x + threadIdx.x;
    if (idx >= HID * N2) return;
    int k = idx / N2, j = idx % N2;
    float v = 0.0f;
    if (j < F2)            v = W2l[k * F2 + j];
    else if (j < 2 * F2)   v = W2r[k * F2 + (j - F2)];
    g_wc2[idx] = v;
}

// ---------------- layer-1 aggregation: build [mean_agg(x) | x] ---------------
__global__ void aggx_kernel(const float* __restrict__ x) {
    int gw   = (blockIdx.x * blockDim.x + threadIdx.x) >> 5;
    int lane = threadIdx.x & 31;
    if (gw >= N_NODES) return;
    int beg = g_rowstart[gw];
    int d   = g_deg[gw];
    float s0 = 0.0f, s1 = 0.0f;
    for (int i = 0; i < d; i++) {
        int s = g_esrc[beg + i];
        const float* xr = x + s * F0;
        s0 += xr[lane];
        if (lane < F0 - 32) s1 += xr[lane + 32];
    }
    float inv = g_invdeg[gw];
    float* o = g_xa + gw * KP1;
    o[lane] = s0 * inv;
    if (lane < F0 - 32) o[lane + 32] = s1 * inv;
    const float* xr = x + gw * F0;
    o[F0 + lane] = xr[lane];
    if (lane < F0 - 32) o[F0 + lane + 32] = xr[lane + 32];
    if (lane < KP1 - 2 * F0) o[2 * F0 + lane] = 0.0f;  // zero pad cols 100..111
}

// ---------------- generic tiled fp32 GEMM body -------------------------------
// C[M x NN] = A[M x KK] * B[KK x NN], M = N_NODES (runtime-guarded), NN,KK padded.
template <int NN, int KK, bool RELU, bool BIAS>
__device__ __forceinline__ void gemm_body(const float* __restrict__ A,
                                          const float* __restrict__ B,
                                          float* __restrict__ C,
                                          const float* __restrict__ bias) {
    constexpr int BM = 64, BN = 64, BK = 16;
    __shared__ float As[BK][BM];
    __shared__ float Bs[BK][BN];
    int tid = threadIdx.x;                 // 256 threads
    int tx = tid & 15, ty = tid >> 4;      // 16 x 16 thread grid
    int rowBase = blockIdx.y * BM;
    int colBase = blockIdx.x * BN;
    int ar = tid >> 2;                     // 0..63
    int ac = (tid & 3) * 4;                // 0,4,8,12
    int br = tid >> 4;                     // 0..15
    int bc = (tid & 15) * 4;               // 0..60

    float acc[4][4];
#pragma unroll
    for (int i = 0; i < 4; i++)
#pragma unroll
        for (int j = 0; j < 4; j++) acc[i][j] = 0.0f;

    for (int k0 = 0; k0 < KK; k0 += BK) {
        float4 av = make_float4(0.f, 0.f, 0.f, 0.f);
        int grow = rowBase + ar;
        if (grow < N_NODES)
            av = *reinterpret_cast<const float4*>(A + (size_t)grow * KK + k0 + ac);
        As[ac + 0][ar] = av.x;
        As[ac + 1][ar] = av.y;
        As[ac + 2][ar] = av.z;
        As[ac + 3][ar] = av.w;
        float4 bv = *reinterpret_cast<const float4*>(B + (size_t)(k0 + br) * NN + colBase + bc);
        *reinterpret_cast<float4*>(&Bs[br][bc]) = bv;
        __syncthreads();
#pragma unroll
        for (int k = 0; k < BK; k++) {
            float4 a = *reinterpret_cast<const float4*>(&As[k][ty * 4]);
            float4 b = *reinterpret_cast<const float4*>(&Bs[k][tx * 4]);
            acc[0][0] += a.x * b.x; acc[0][1] += a.x * b.y; acc[0][2] += a.x * b.z; acc[0][3] += a.x * b.w;
            acc[1][0] += a.y * b.x; acc[1][1] += a.y * b.y; acc[1][2] += a.y * b.z; acc[1][3] += a.y * b.w;
            acc[2][0] += a.z * b.x; acc[2][1] += a.z * b.y; acc[2][2] += a.z * b.z; acc[2][3] += a.z * b.w;
            acc[3][0] += a.w * b.x; acc[3][1] += a.w * b.y; acc[3][2] += a.w * b.z; acc[3][3] += a.w * b.w;
        }
        __syncthreads();
    }

#pragma unroll
    for (int i = 0; i < 4; i++) {
        int r = rowBase + ty * 4 + i;
        if (r < N_NODES) {
            float4 c;
            c.x = acc[i][0]; c.y = acc[i][1]; c.z = acc[i][2]; c.w = acc[i][3];
            if (BIAS) {
                const float* bp = bias + colBase + tx * 4;
                c.x += bp[0]; c.y += bp[1]; c.z += bp[2]; c.w += bp[3];
            }
            if (RELU) {
                c.x = fmaxf(c.x, 0.f); c.y = fmaxf(c.y, 0.f);
                c.z = fmaxf(c.z, 0.f); c.w = fmaxf(c.w, 0.f);
            }
            *reinterpret_cast<float4*>(C + (size_t)r * NN + colBase + tx * 4) = c;
        }
    }
}

__global__ void gemm1_kernel(const float* __restrict__ b1) {
    gemm_body<HID, KP1, true, true>(g_xa, g_wc1, g_h, b1);
}
__global__ void gemm2_kernel() {
    gemm_body<N2, HID, false, false>(g_h, g_wc2, g_qr, nullptr);
}

// ---------------- final: out = mean_agg(q) + r + b2 --------------------------
__global__ void final_kernel(const float* __restrict__ b2, float* __restrict__ out) {
    int gw   = (blockIdx.x * blockDim.x + threadIdx.x) >> 5;
    int lane = threadIdx.x & 31;
    if (gw >= N_NODES) return;
    int beg = g_rowstart[gw];
    int d   = g_deg[gw];
    int j4  = lane * 4;                    // 0..124, all < N2 (safe reads)
    float4 acc = make_float4(0.f, 0.f, 0.f, 0.f);
    for (int i = 0; i < d; i++) {
        int s = g_esrc[beg + i];
        float4 v = *reinterpret_cast<const float4*>(g_qr + (size_t)s * N2 + j4);
        acc.x += v.x; acc.y += v.y; acc.z += v.z; acc.w += v.w;
    }
    float inv = g_invdeg[gw];
    const float* rrow = g_qr + (size_t)gw * N2 + F2;
    float* orow = out + (size_t)gw * F2;
    float av[4] = {acc.x, acc.y, acc.z, acc.w};
#pragma unroll
    for (int c = 0; c < 4; c++) {
        int jj = j4 + c;
        if (jj < F2) orow[jj] = av[c] * inv + rrow[jj] + b2[jj];
    }
}

// ---------------- launch ------------------------------------------------------
extern "C" void kernel_launch(void* const* d_in, const int* in_sizes, int n_in,
                              void* d_out, int out_size) {
    const float* x   = (const float*)d_in[0];
    const void*  ei  = d_in[1];
    const float* W1l = (const float*)d_in[2];
    const float* W1r = (const float*)d_in[3];
    const float* b1  = (const float*)d_in[4];
    const float* W2l = (const float*)d_in[5];
    const float* W2r = (const float*)d_in[6];
    const float* b2  = (const float*)d_in[7];
    float*       out = (float*)d_out;

    detect_kernel<<<1, 32>>>((const int*)ei);
    zero_deg_kernel<<<(N_NODES + 255) / 256, 256>>>();
    count_kernel<<<(N_EDGES + 255) / 256, 256>>>(ei);
    wc1_kernel<<<(KP1 * HID + 255) / 256, 256>>>(W1l, W1r);
    wc2_kernel<<<(HID * N2 + 255) / 256, 256>>>(W2l, W2r);
    scan_kernel<<<1, 1024>>>();
    bucket_kernel<<<(N_EDGES + 255) / 256, 256>>>(ei);
    aggx_kernel<<<(N_NODES + 7) / 8, 256>>>(x);
    gemm1_kernel<<<dim3(HID / 64, (N_NODES + 63) / 64), 256>>>(b1);
    gemm2_kernel<<<dim3(N2 / 64, (N_NODES + 63) / 64), 256>>>();
    final_kernel<<<(N_NODES + 7) / 8, 256>>>(b2, out);
}

// round 6
// speedup vs baseline: 2.0442x; 2.0442x over previous
#include <cuda_runtime.h>
#include <cuda_bf16.h>
#include <cstdint>

#define N_NODES 10000
#define M_PAD   10112     // 79 tiles of 128
#define N_EDGES 160000
#define F0      50
#define HID     512
#define F2      121
#define N2      256
#define KP1     384       // layer-1 packed K: 3*112 (pad 336->384)
#define KP2     1536      // layer-2 packed K: 3*512

// ---------------- scratch (device globals; zero-initialized) -----------------
__device__ int   g_is64;
__device__ int   g_deg[N_NODES];
__device__ int   g_rowstart[N_NODES];
__device__ int   g_cursor[N_NODES];
__device__ float g_invdeg[N_NODES];
__device__ int   g_esrc[N_EDGES];
__device__ __align__(16) __nv_bfloat16 g_a1[(size_t)M_PAD * KP1];   // [agg|self] hi|hi|lo
__device__ __align__(16) __nv_bfloat16 g_b1p[(size_t)HID * KP1];    // W1 packed hi|lo|hi (row=n)
__device__ __align__(16) __nv_bfloat16 g_a2[(size_t)M_PAD * KP2];   // h packed hi|hi|lo
__device__ __align__(16) __nv_bfloat16 g_b2p[(size_t)N2 * KP2];     // W2 packed hi|lo|hi
__device__ __align__(16) float g_qr[(size_t)M_PAD * N2];            // [q | r | pad]

// ---------------- PTX helpers -------------------------------------------------
__device__ __forceinline__ uint32_t smem_u32(const void* p) {
    uint32_t a;
    asm("{ .reg .u64 t; cvta.to.shared.u64 t, %1; cvt.u32.u64 %0, t; }" : "=r"(a) : "l"(p));
    return a;
}
#define CP16(dst, src) \
    asm volatile("cp.async.cg.shared.global [%0], [%1], 16;" :: "r"(dst), "l"(src) : "memory")
#define CP_COMMIT() asm volatile("cp.async.commit_group;" ::: "memory")
#define CP_WAIT(n)  asm volatile("cp.async.wait_group %0;" :: "n"(n) : "memory")

__device__ __forceinline__ void mma16816(float* d, const uint32_t* a, const uint32_t* b) {
    asm volatile(
        "mma.sync.aligned.m16n8k16.row.col.f32.bf16.bf16.f32 "
        "{%0,%1,%2,%3}, {%4,%5,%6,%7}, {%8,%9}, {%0,%1,%2,%3};"
        : "+f"(d[0]), "+f"(d[1]), "+f"(d[2]), "+f"(d[3])
        : "r"(a[0]), "r"(a[1]), "r"(a[2]), "r"(a[3]), "r"(b[0]), "r"(b[1]));
}

// ---------------- edge-index dtype detection + deg zero ----------------------
__global__ void detect_zero_kernel(const int* __restrict__ ei32) {
    int i = blockIdx.x * blockDim.x + threadIdx.x;
    if (i < N_NODES) g_deg[i] = 0;
    if (i == 0) {
        int odd_nonzero = 0;
        for (int k = 1; k < 4096; k += 2) odd_nonzero |= (ei32[k] != 0);
        g_is64 = odd_nonzero ? 0 : 1;
    }
}
__device__ __forceinline__ int load_idx(const void* ei, int pos) {
    int v = g_is64 ? (int)((const long long*)ei)[pos] : ((const int*)ei)[pos];
    return min(max(v, 0), N_NODES - 1);
}

// ---------------- CSR build --------------------------------------------------
__global__ void count_kernel(const void* __restrict__ ei) {
    int e = blockIdx.x * blockDim.x + threadIdx.x;
    if (e < N_EDGES) atomicAdd(&g_deg[load_idx(ei, N_EDGES + e)], 1);
}
__global__ void scan_kernel() {
    const int CH = 10;
    __shared__ int s[1024];
    int t = threadIdx.x, base = t * CH, local[CH], sum = 0;
#pragma unroll
    for (int i = 0; i < CH; i++) {
        int idx = base + i;
        int v = (idx < N_NODES) ? g_deg[idx] : 0;
        local[i] = v; sum += v;
    }
    s[t] = sum; __syncthreads();
    for (int off = 1; off < 1024; off <<= 1) {
        int v = (t >= off) ? s[t - off] : 0;
        __syncthreads(); s[t] += v; __syncthreads();
    }
    int excl = s[t] - sum;
#pragma unroll
    for (int i = 0; i < CH; i++) {
        int idx = base + i;
        if (idx < N_NODES) {
            g_rowstart[idx] = excl; g_cursor[idx] = excl;
            int d = local[i];
            g_invdeg[idx] = 1.0f / (float)(d > 1 ? d : 1);
            excl += d;
        }
    }
}
__global__ void bucket_kernel(const void* __restrict__ ei) {
    int e = blockIdx.x * blockDim.x + threadIdx.x;
    if (e < N_EDGES) {
        int dst = load_idx(ei, N_EDGES + e);
        int pos = atomicAdd(&g_cursor[dst], 1);
        pos = min(max(pos, 0), N_EDGES - 1);
        g_esrc[pos] = load_idx(ei, e);
    }
}

// ---------------- hi/lo helpers ----------------------------------------------
__device__ __forceinline__ void hilo(float v, __nv_bfloat16& h, __nv_bfloat16& l) {
    h = __float2bfloat16_rn(v);
    l = __float2bfloat16_rn(v - __bfloat162float(h));
}

// ---------------- layer-1 aggregation + A1 pack ------------------------------
// a1 row (K'=384): [0,112)=hi(xa), [112,224)=hi(xa), [224,336)=lo(xa), rest 0
// xa = [agg(50) | self(50) | 12 zeros]
__global__ void aggx_pack_kernel(const float* __restrict__ x) {
    int gw = (blockIdx.x * blockDim.x + threadIdx.x) >> 5;
    int lane = threadIdx.x & 31;
    if (gw >= N_NODES) return;
    int beg = g_rowstart[gw], d = g_deg[gw];
    float s0 = 0.f, s1 = 0.f;
    for (int i = 0; i < d; i++) {
        int s = g_esrc[beg + i];
        const float* xr = x + s * F0;
        s0 += xr[lane];
        if (lane < F0 - 32) s1 += xr[lane + 32];
    }
    float inv = g_invdeg[gw];
    const float* xs = x + gw * F0;
    size_t rb = (size_t)gw * KP1;
    __nv_bfloat16 h, l;
#define WR_A1(j, v) do { hilo((v), h, l); g_a1[rb + (j)] = h; g_a1[rb + 112 + (j)] = h; g_a1[rb + 224 + (j)] = l; } while (0)
    WR_A1(lane, s0 * inv);
    if (lane < F0 - 32) WR_A1(lane + 32, s1 * inv);
    WR_A1(F0 + lane, xs[lane]);
    if (lane < F0 - 32) WR_A1(F0 + lane + 32, xs[lane + 32]);
#undef WR_A1
}

// ---------------- weight packs -----------------------------------------------
__global__ void packW1_kernel(const float* __restrict__ W1l, const float* __restrict__ W1r) {
    int idx = blockIdx.x * blockDim.x + threadIdx.x;
    if (idx >= HID * 112) return;
    int k = idx % 112, n = idx / 112;
    float v = 0.f;
    if (k < F0)            v = W1l[k * HID + n];
    else if (k < 2 * F0)   v = W1r[(k - F0) * HID + n];
    __nv_bfloat16 h, l; hilo(v, h, l);
    size_t rb = (size_t)n * KP1;
    g_b1p[rb + k] = h; g_b1p[rb + 112 + k] = l; g_b1p[rb + 224 + k] = h;
}
__global__ void packW2_kernel(const float* __restrict__ W2l, const float* __restrict__ W2r) {
    int idx = blockIdx.x * blockDim.x + threadIdx.x;
    if (idx >= N2 * HID) return;
    int k = idx % HID, n = idx / HID;
    float v = 0.f;
    if (n < F2)            v = W2l[k * F2 + n];
    else if (n < 2 * F2)   v = W2r[k * F2 + (n - F2)];
    __nv_bfloat16 h, l; hilo(v, h, l);
    size_t rb = (size_t)n * KP2;
    g_b2p[rb + k] = h; g_b2p[rb + 512 + k] = l; g_b2p[rb + 1024 + k] = h;
}

// ---------------- mma.sync GEMM: C[128x128 tile] = A B^T ---------------------
// A row-major [M][KP]; B row-major by output col: Bg[n][k] ("col" operand).
// MODE 1: A=g_a1 (KP1), B=g_b1p, epilogue bias+relu -> pack g_a2 (hi|hi|lo)
// MODE 2: A=g_a2 (KP2), B=g_b2p, epilogue fp32 -> g_qr
#define BK      64
#define LDPAD   72        // bf16 elems per smem row (64 + 8 pad) = 144B
#define TILE_B  (128 * LDPAD * 2)   // 18432 bytes per operand per stage

template <int MODE>
__global__ void __launch_bounds__(256) mma_gemm_kernel(const float* __restrict__ bias) {
    constexpr int KP = (MODE == 1) ? KP1 : KP2;
    constexpr int C  = KP / BK;
    const __nv_bfloat16* Ag = (MODE == 1) ? g_a1 : g_a2;
    const __nv_bfloat16* Bg = (MODE == 1) ? g_b1p : g_b2p;

    extern __shared__ __align__(16) char dsm[];
    // layout: stage s: A at s*2*TILE_B, B at s*2*TILE_B + TILE_B
    uint32_t sb = smem_u32(dsm);

    int tid = threadIdx.x, wid = tid >> 5, lane = tid & 31;
    int wm = wid & 1, wn = wid >> 1;       // warp grid 2 (M) x 4 (N)
    int mbase = blockIdx.y * 128, nbase = blockIdx.x * 128;

    float acc[4][4][4];
#pragma unroll
    for (int i = 0; i < 4; i++)
#pragma unroll
        for (int j = 0; j < 4; j++)
#pragma unroll
            for (int k = 0; k < 4; k++) acc[i][j][k] = 0.f;

    int lr = lane >> 2;           // 0..7
    int lc = lane & 3;            // 0..3

    // ---- stage loader ----
    auto load_chunk = [&](int c, int s) {
        uint32_t da = sb + s * 2 * TILE_B;
        uint32_t db = da + TILE_B;
        const __nv_bfloat16* asrc = Ag + (size_t)mbase * KP + c * BK;
        const __nv_bfloat16* bsrc = Bg + (size_t)nbase * KP + c * BK;
#pragma unroll
        for (int i = 0; i < 4; i++) {
            int seg = tid + i * 256;          // 0..1023
            int row = seg >> 3, s16 = seg & 7;
            uint32_t off = row * (LDPAD * 2) + s16 * 16;
            CP16(da + off, asrc + (size_t)row * KP + s16 * 8);
            CP16(db + off, bsrc + (size_t)row * KP + s16 * 8);
        }
        CP_COMMIT();
    };

    load_chunk(0, 0);

    for (int c = 0; c < C; ++c) {
        int s = c & 1;
        if (c + 1 < C) { load_chunk(c + 1, s ^ 1); CP_WAIT(1); }
        else           { CP_WAIT(0); }
        __syncthreads();

        const char* As = dsm + s * 2 * TILE_B;
        const char* Bs = As + TILE_B;
#pragma unroll
        for (int k16 = 0; k16 < BK / 16; ++k16) {
            int ka = k16 * 16 + lc * 2;       // A col of first u32
            uint32_t afr[4][4], bfr[4][2];
#pragma unroll
            for (int mi = 0; mi < 4; mi++) {
                int r0 = wm * 64 + mi * 16 + lr;
                const uint32_t* p0 = (const uint32_t*)(As + r0 * (LDPAD * 2));
                const uint32_t* p1 = (const uint32_t*)(As + (r0 + 8) * (LDPAD * 2));
                afr[mi][0] = p0[ka >> 1];
                afr[mi][1] = p1[ka >> 1];
                afr[mi][2] = p0[(ka + 8) >> 1];
                afr[mi][3] = p1[(ka + 8) >> 1];
            }
#pragma unroll
            for (int ni = 0; ni < 4; ni++) {
                int n0 = wn * 32 + ni * 8 + lr;
                const uint32_t* q = (const uint32_t*)(Bs + n0 * (LDPAD * 2));
                bfr[ni][0] = q[ka >> 1];
                bfr[ni][1] = q[(ka + 8) >> 1];
            }
#pragma unroll
            for (int mi = 0; mi < 4; mi++)
#pragma unroll
                for (int ni = 0; ni < 4; ni++)
                    mma16816(acc[mi][ni], afr[mi], bfr[ni]);
        }
        __syncthreads();
    }

    // ---- epilogue ----
#pragma unroll
    for (int mi = 0; mi < 4; mi++) {
        int row0 = mbase + wm * 64 + mi * 16 + lr;
        int row1 = row0 + 8;
#pragma unroll
        for (int ni = 0; ni < 4; ni++) {
            int col0 = nbase + wn * 32 + ni * 8 + lc * 2;
            float* d = acc[mi][ni];
            if (MODE == 1) {
                float bb0 = bias[col0], bb1 = bias[col0 + 1];
#pragma unroll
                for (int half = 0; half < 2; half++) {
                    int r = half ? row1 : row0;
                    if (r >= N_NODES) continue;
                    float v0 = fmaxf(d[half * 2 + 0] + bb0, 0.f);
                    float v1 = fmaxf(d[half * 2 + 1] + bb1, 0.f);
                    __nv_bfloat16 h0, l0, h1, l1;
                    hilo(v0, h0, l0); hilo(v1, h1, l1);
                    size_t rb = (size_t)r * KP2;
                    g_a2[rb + col0] = h0;        g_a2[rb + col0 + 1] = h1;
                    g_a2[rb + 512 + col0] = h0;  g_a2[rb + 512 + col0 + 1] = h1;
                    g_a2[rb + 1024 + col0] = l0; g_a2[rb + 1024 + col0 + 1] = l1;
                }
            } else {
                if (row0 < N_NODES) {
                    g_qr[(size_t)row0 * N2 + col0]     = d[0];
                    g_qr[(size_t)row0 * N2 + col0 + 1] = d[1];
                }
                if (row1 < N_NODES) {
                    g_qr[(size_t)row1 * N2 + col0]     = d[2];
                    g_qr[(size_t)row1 * N2 + col0 + 1] = d[3];
                }
            }
        }
    }
}

// ---------------- final: out = mean_agg(q) + r + b2 --------------------------
__global__ void final_kernel(const float* __restrict__ b2, float* __restrict__ out) {
    int gw = (blockIdx.x * blockDim.x + threadIdx.x) >> 5;
    int lane = threadIdx.x & 31;
    if (gw >= N_NODES) return;
    int beg = g_rowstart[gw], d = g_deg[gw];
    int j4 = lane * 4;
    float4 acc = make_float4(0.f, 0.f, 0.f, 0.f);
    for (int i = 0; i < d; i++) {
        int s = g_esrc[beg + i];
        float4 v = *reinterpret_cast<const float4*>(g_qr + (size_t)s * N2 + j4);
        acc.x += v.x; acc.y += v.y; acc.z += v.z; acc.w += v.w;
    }
    float inv = g_invdeg[gw];
    const float* rrow = g_qr + (size_t)gw * N2 + F2;
    float* orow = out + (size_t)gw * F2;
    float av[4] = {acc.x, acc.y, acc.z, acc.w};
#pragma unroll
    for (int c = 0; c < 4; c++) {
        int jj = j4 + c;
        if (jj < F2) orow[jj] = av[c] * inv + rrow[jj] + b2[jj];
    }
}

// ---------------- launch ------------------------------------------------------
extern "C" void kernel_launch(void* const* d_in, const int* in_sizes, int n_in,
                              void* d_out, int out_size) {
    const float* x   = (const float*)d_in[0];
    const void*  ei  = d_in[1];
    const float* W1l = (const float*)d_in[2];
    const float* W1r = (const float*)d_in[3];
    const float* b1  = (const float*)d_in[4];
    const float* W2l = (const float*)d_in[5];
    const float* W2r = (const float*)d_in[6];
    const float* b2  = (const float*)d_in[7];
    float*       out = (float*)d_out;

    const int SMEM_DYN = 4 * TILE_B;   // 73728 bytes: 2 stages x (A + B)
    static bool attr_set = false;
    if (!attr_set) {
        cudaFuncSetAttribute(mma_gemm_kernel<1>, cudaFuncAttributeMaxDynamicSharedMemorySize, SMEM_DYN);
        cudaFuncSetAttribute(mma_gemm_kernel<2>, cudaFuncAttributeMaxDynamicSharedMemorySize, SMEM_DYN);
        attr_set = true;
    }

    detect_zero_kernel<<<(N_NODES + 255) / 256, 256>>>((const int*)ei);
    count_kernel<<<(N_EDGES + 255) / 256, 256>>>(ei);
    packW1_kernel<<<(HID * 112 + 255) / 256, 256>>>(W1l, W1r);
    packW2_kernel<<<(N2 * HID + 255) / 256, 256>>>(W2l, W2r);
    scan_kernel<<<1, 1024>>>();
    bucket_kernel<<<(N_EDGES + 255) / 256, 256>>>(ei);
    aggx_pack_kernel<<<(N_NODES * 32 + 255) / 256, 256>>>(x);
    mma_gemm_kernel<1><<<dim3(HID / 128, M_PAD / 128), 256, SMEM_DYN>>>(b1);
    mma_gemm_kernel<2><<<dim3(N2 / 128, M_PAD / 128), 256, SMEM_DYN>>>(nullptr);
    final_kernel<<<(N_NODES + 7) / 8, 256>>>(b2, out);
}

// round 7
// speedup vs baseline: 2.1908x; 1.0717x over previous
#include <cuda_runtime.h>
#include <cuda_bf16.h>
#include <cstdint>

#define N_NODES 10000
#define M_PAD   10112     // 79 tiles of 128
#define N_EDGES 160000
#define F0      50
#define HID     512
#define F2      121
#define N2      256
// layer 1: logical K' = 3*128 = 384 (panel width 128, data 112 used)
//   A stored 2 panels [hi|lo] = 256 cols ; B stored 3 panels [hi|lo|hi] = 384
// layer 2: logical K' = 3*512 = 1536
//   A stored 2 panels [hi|lo] = 1024 cols ; B stored 3 panels [hi|lo|hi] = 1536
#define KA1     256
#define KB1     384
#define KA2     1024
#define KB2     1536

// ---------------- scratch (device globals; zero-initialized) -----------------
__device__ int   g_is64;
__device__ int   g_deg[N_NODES];
__device__ int   g_rowstart[N_NODES];
__device__ int   g_cursor[N_NODES];
__device__ float g_invdeg[N_NODES];
__device__ int   g_esrc[N_EDGES];
__device__ __align__(16) __nv_bfloat16 g_a1[(size_t)M_PAD * KA1];
__device__ __align__(16) __nv_bfloat16 g_b1p[(size_t)HID * KB1];
__device__ __align__(16) __nv_bfloat16 g_a2[(size_t)M_PAD * KA2];
__device__ __align__(16) __nv_bfloat16 g_b2p[(size_t)N2 * KB2];
__device__ __align__(16) float g_qr[(size_t)M_PAD * N2];            // [q | r | pad]

// ---------------- PTX helpers -------------------------------------------------
__device__ __forceinline__ uint32_t smem_u32(const void* p) {
    uint32_t a;
    asm("{ .reg .u64 t; cvta.to.shared.u64 t, %1; cvt.u32.u64 %0, t; }" : "=r"(a) : "l"(p));
    return a;
}
#define CP16(dst, src) \
    asm volatile("cp.async.cg.shared.global [%0], [%1], 16;" :: "r"(dst), "l"(src) : "memory")
#define CP_COMMIT() asm volatile("cp.async.commit_group;" ::: "memory")
#define CP_WAIT(n)  asm volatile("cp.async.wait_group %0;" :: "n"(n) : "memory")
#define LDSM_X4(r0, r1, r2, r3, addr) \
    asm volatile("ldmatrix.sync.aligned.m8n8.x4.shared.b16 {%0,%1,%2,%3}, [%4];" \
                 : "=r"(r0), "=r"(r1), "=r"(r2), "=r"(r3) : "r"(addr))
#define LDSM_X2(r0, r1, addr) \
    asm volatile("ldmatrix.sync.aligned.m8n8.x2.shared.b16 {%0,%1}, [%2];" \
                 : "=r"(r0), "=r"(r1) : "r"(addr))

__device__ __forceinline__ void mma16816(float* d, const uint32_t* a, const uint32_t* b) {
    asm volatile(
        "mma.sync.aligned.m16n8k16.row.col.f32.bf16.bf16.f32 "
        "{%0,%1,%2,%3}, {%4,%5,%6,%7}, {%8,%9}, {%0,%1,%2,%3};"
        : "+f"(d[0]), "+f"(d[1]), "+f"(d[2]), "+f"(d[3])
        : "r"(a[0]), "r"(a[1]), "r"(a[2]), "r"(a[3]), "r"(b[0]), "r"(b[1]));
}

// ---------------- edge-index dtype detection + deg zero ----------------------
__global__ void detect_zero_kernel(const int* __restrict__ ei32) {
    int i = blockIdx.x * blockDim.x + threadIdx.x;
    if (i < N_NODES) g_deg[i] = 0;
    if (i == 0) {
        int odd_nonzero = 0;
        for (int k = 1; k < 4096; k += 2) odd_nonzero |= (ei32[k] != 0);
        g_is64 = odd_nonzero ? 0 : 1;
    }
}
__device__ __forceinline__ int load_idx(const void* ei, int pos) {
    int v = g_is64 ? (int)((const long long*)ei)[pos] : ((const int*)ei)[pos];
    return min(max(v, 0), N_NODES - 1);
}

// ---------------- CSR build --------------------------------------------------
__global__ void count_kernel(const void* __restrict__ ei) {
    int e = blockIdx.x * blockDim.x + threadIdx.x;
    if (e < N_EDGES) atomicAdd(&g_deg[load_idx(ei, N_EDGES + e)], 1);
}
__global__ void scan_kernel() {
    const int CH = 10;
    __shared__ int s[1024];
    int t = threadIdx.x, base = t * CH, local[CH], sum = 0;
#pragma unroll
    for (int i = 0; i < CH; i++) {
        int idx = base + i;
        int v = (idx < N_NODES) ? g_deg[idx] : 0;
        local[i] = v; sum += v;
    }
    s[t] = sum; __syncthreads();
    for (int off = 1; off < 1024; off <<= 1) {
        int v = (t >= off) ? s[t - off] : 0;
        __syncthreads(); s[t] += v; __syncthreads();
    }
    int excl = s[t] - sum;
#pragma unroll
    for (int i = 0; i < CH; i++) {
        int idx = base + i;
        if (idx < N_NODES) {
            g_rowstart[idx] = excl; g_cursor[idx] = excl;
            int d = local[i];
            g_invdeg[idx] = 1.0f / (float)(d > 1 ? d : 1);
            excl += d;
        }
    }
}
__global__ void bucket_kernel(const void* __restrict__ ei) {
    int e = blockIdx.x * blockDim.x + threadIdx.x;
    if (e < N_EDGES) {
        int dst = load_idx(ei, N_EDGES + e);
        int pos = atomicAdd(&g_cursor[dst], 1);
        pos = min(max(pos, 0), N_EDGES - 1);
        g_esrc[pos] = load_idx(ei, e);
    }
}

// ---------------- hi/lo helpers ----------------------------------------------
__device__ __forceinline__ void hilo(float v, __nv_bfloat16& h, __nv_bfloat16& l) {
    h = __float2bfloat16_rn(v);
    l = __float2bfloat16_rn(v - __bfloat162float(h));
}

// ---------------- layer-1 aggregation + A1 pack (2 panels: hi | lo) ----------
__global__ void aggx_pack_kernel(const float* __restrict__ x) {
    int gw = (blockIdx.x * blockDim.x + threadIdx.x) >> 5;
    int lane = threadIdx.x & 31;
    if (gw >= N_NODES) return;
    int beg = g_rowstart[gw], d = g_deg[gw];
    float s0 = 0.f, s1 = 0.f;
    for (int i = 0; i < d; i++) {
        int s = g_esrc[beg + i];
        const float* xr = x + s * F0;
        s0 += xr[lane];
        if (lane < F0 - 32) s1 += xr[lane + 32];
    }
    float inv = g_invdeg[gw];
    const float* xs = x + gw * F0;
    size_t rb = (size_t)gw * KA1;
    __nv_bfloat16 h, l;
#define WR_A1(j, v) do { hilo((v), h, l); g_a1[rb + (j)] = h; g_a1[rb + 128 + (j)] = l; } while (0)
    WR_A1(lane, s0 * inv);
    if (lane < F0 - 32) WR_A1(lane + 32, s1 * inv);
    WR_A1(F0 + lane, xs[lane]);
    if (lane < F0 - 32) WR_A1(F0 + lane + 32, xs[lane + 32]);
#undef WR_A1
}

// ---------------- weight packs (merged) --------------------------------------
// W1: row n (<512), k<112: hi at k, lo at 128+k, hi at 256+k (panel width 128)
// W2: row n (<256), k<512: hi at k, lo at 512+k, hi at 1024+k
__global__ void packW_kernel(const float* __restrict__ W1l, const float* __restrict__ W1r,
                             const float* __restrict__ W2l, const float* __restrict__ W2r) {
    int idx = blockIdx.x * blockDim.x + threadIdx.x;
    if (idx < HID * 112) {
        int k = idx % 112, n = idx / 112;
        float v = 0.f;
        if (k < F0)            v = W1l[k * HID + n];
        else if (k < 2 * F0)   v = W1r[(k - F0) * HID + n];
        __nv_bfloat16 h, l; hilo(v, h, l);
        size_t rb = (size_t)n * KB1;
        g_b1p[rb + k] = h; g_b1p[rb + 128 + k] = l; g_b1p[rb + 256 + k] = h;
    } else {
        int i2 = idx - HID * 112;
        if (i2 >= N2 * HID) return;
        int k = i2 % HID, n = i2 / HID;
        float v = 0.f;
        if (n < F2)            v = W2l[k * F2 + n];
        else if (n < 2 * F2)   v = W2r[k * F2 + (n - F2)];
        __nv_bfloat16 h, l; hilo(v, h, l);
        size_t rb = (size_t)n * KB2;
        g_b2p[rb + k] = h; g_b2p[rb + 512 + k] = l; g_b2p[rb + 1024 + k] = h;
    }
}

// ---------------- mma.sync GEMM: C[128x128 tile] = A B^T ---------------------
// Logical K' split into BK=64 chunks; A chunk source offset given by AOFF(c)
// (hi panel reused), B chunk at c*64.
#define BK      64
#define LDPAD   72        // bf16 elems per smem row (64 + 8 pad) = 144B
#define ROWB    (LDPAD * 2)
#define TILE_B  (128 * ROWB)        // 18432 bytes per operand per stage

template <int MODE>
__global__ void __launch_bounds__(256) mma_gemm_kernel(const float* __restrict__ bias) {
    constexpr int C  = (MODE == 1) ? 6 : 24;
    constexpr int KA = (MODE == 1) ? KA1 : KA2;
    constexpr int KB = (MODE == 1) ? KB1 : KB2;
    const __nv_bfloat16* Ag = (MODE == 1) ? g_a1 : g_a2;
    const __nv_bfloat16* Bg = (MODE == 1) ? g_b1p : g_b2p;

    extern __shared__ __align__(16) char dsm[];
    uint32_t sb = smem_u32(dsm);

    int tid = threadIdx.x, wid = tid >> 5, lane = tid & 31;
    int wm = wid & 1, wn = wid >> 1;       // warp grid 2 (M) x 4 (N)
    int mbase = blockIdx.y * 128, nbase = blockIdx.x * 128;

    float acc[4][4][4];
#pragma unroll
    for (int i = 0; i < 4; i++)
#pragma unroll
        for (int j = 0; j < 4; j++)
#pragma unroll
            for (int k = 0; k < 4; k++) acc[i][j][k] = 0.f;

    // ldmatrix per-lane offsets (within an operand stage)
    uint32_t a_off[4], b_off[4];
#pragma unroll
    for (int mi = 0; mi < 4; mi++)
        a_off[mi] = (uint32_t)(wm * 64 + mi * 16 + (lane & 15)) * ROWB + (uint32_t)(lane >> 4) * 16u;
#pragma unroll
    for (int ni = 0; ni < 4; ni++)
        b_off[ni] = (uint32_t)(wn * 32 + ni * 8 + (lane & 7)) * ROWB + (uint32_t)((lane >> 3) & 1) * 16u;

    auto aoff_of = [](int c) -> int {
        if (MODE == 1) { // panels 128 wide: chunks {hi0,hi1, hi0,hi1, lo0,lo1}
            const int m[6] = {0, 64, 0, 64, 128, 192};
            return m[c];
        } else {         // panels 512 wide: 0-7 hi, 8-15 hi, 16-23 lo
            return (c < 16) ? (c & 7) * 64 : 512 + (c - 16) * 64;
        }
    };

    auto load_chunk = [&](int c, int s) {
        uint32_t da = sb + s * 2 * TILE_B;
        uint32_t db = da + TILE_B;
        const __nv_bfloat16* asrc = Ag + (size_t)mbase * KA + aoff_of(c);
        const __nv_bfloat16* bsrc = Bg + (size_t)nbase * KB + c * BK;
#pragma unroll
        for (int i = 0; i < 4; i++) {
            int seg = tid + i * 256;          // 0..1023
            int row = seg >> 3, s16 = seg & 7;
            uint32_t off = row * ROWB + s16 * 16;
            CP16(da + off, asrc + (size_t)row * KA + s16 * 8);
            CP16(db + off, bsrc + (size_t)row * KB + s16 * 8);
        }
        CP_COMMIT();
    };

    load_chunk(0, 0);

    for (int c = 0; c < C; ++c) {
        int s = c & 1;
        if (c + 1 < C) { load_chunk(c + 1, s ^ 1); CP_WAIT(1); }
        else           { CP_WAIT(0); }
        __syncthreads();

        uint32_t As = sb + s * 2 * TILE_B;
        uint32_t Bs = As + TILE_B;
#pragma unroll
        for (int k16 = 0; k16 < BK / 16; ++k16) {
            uint32_t afr[4][4], bfr[4][2];
#pragma unroll
            for (int mi = 0; mi < 4; mi++)
                LDSM_X4(afr[mi][0], afr[mi][1], afr[mi][2], afr[mi][3],
                        As + a_off[mi] + k16 * 32u);
#pragma unroll
            for (int ni = 0; ni < 4; ni++)
                LDSM_X2(bfr[ni][0], bfr[ni][1], Bs + b_off[ni] + k16 * 32u);
#pragma unroll
            for (int mi = 0; mi < 4; mi++)
#pragma unroll
                for (int ni = 0; ni < 4; ni++)
                    mma16816(acc[mi][ni], afr[mi], bfr[ni]);
        }
        __syncthreads();
    }

    // ---- epilogue ----
    int lr = lane >> 2, lc = lane & 3;
#pragma unroll
    for (int mi = 0; mi < 4; mi++) {
        int row0 = mbase + wm * 64 + mi * 16 + lr;
        int row1 = row0 + 8;
#pragma unroll
        for (int ni = 0; ni < 4; ni++) {
            int col0 = nbase + wn * 32 + ni * 8 + lc * 2;
            float* d = acc[mi][ni];
            if (MODE == 1) {
                float bb0 = bias[col0], bb1 = bias[col0 + 1];
#pragma unroll
                for (int half = 0; half < 2; half++) {
                    int r = half ? row1 : row0;
                    if (r >= N_NODES) continue;
                    float v0 = fmaxf(d[half * 2 + 0] + bb0, 0.f);
                    float v1 = fmaxf(d[half * 2 + 1] + bb1, 0.f);
                    __nv_bfloat16 h0, l0, h1, l1;
                    hilo(v0, h0, l0); hilo(v1, h1, l1);
                    size_t rb = (size_t)r * KA2;
                    __nv_bfloat162 hp; hp.x = h0; hp.y = h1;
                    __nv_bfloat162 lp; lp.x = l0; lp.y = l1;
                    *reinterpret_cast<__nv_bfloat162*>(&g_a2[rb + col0]) = hp;
                    *reinterpret_cast<__nv_bfloat162*>(&g_a2[rb + 512 + col0]) = lp;
                }
            } else {
                if (row0 < N_NODES)
                    *reinterpret_cast<float2*>(&g_qr[(size_t)row0 * N2 + col0]) =
                        make_float2(d[0], d[1]);
                if (row1 < N_NODES)
                    *reinterpret_cast<float2*>(&g_qr[(size_t)row1 * N2 + col0]) =
                        make_float2(d[2], d[3]);
            }
        }
    }
}

// ---------------- final: out = mean_agg(q) + r + b2 --------------------------
__global__ void final_kernel(const float* __restrict__ b2, float* __restrict__ out) {
    int gw = (blockIdx.x * blockDim.x + threadIdx.x) >> 5;
    int lane = threadIdx.x & 31;
    if (gw >= N_NODES) return;
    int beg = g_rowstart[gw], d = g_deg[gw];
    int j4 = lane * 4;
    float4 acc = make_float4(0.f, 0.f, 0.f, 0.f);
    for (int i = 0; i < d; i++) {
        int s = g_esrc[beg + i];
        float4 v = *reinterpret_cast<const float4*>(g_qr + (size_t)s * N2 + j4);
        acc.x += v.x; acc.y += v.y; acc.z += v.z; acc.w += v.w;
    }
    float inv = g_invdeg[gw];
    const float* rrow = g_qr + (size_t)gw * N2 + F2;
    float* orow = out + (size_t)gw * F2;
    float av[4] = {acc.x, acc.y, acc.z, acc.w};
#pragma unroll
    for (int c = 0; c < 4; c++) {
        int jj = j4 + c;
        if (jj < F2) orow[jj] = av[c] * inv + rrow[jj] + b2[jj];
    }
}

// ---------------- launch ------------------------------------------------------
extern "C" void kernel_launch(void* const* d_in, const int* in_sizes, int n_in,
                              void* d_out, int out_size) {
    const float* x   = (const float*)d_in[0];
    const void*  ei  = d_in[1];
    const float* W1l = (const float*)d_in[2];
    const float* W1r = (const float*)d_in[3];
    const float* b1  = (const float*)d_in[4];
    const float* W2l = (const float*)d_in[5];
    const float* W2r = (const float*)d_in[6];
    const float* b2  = (const float*)d_in[7];
    float*       out = (float*)d_out;

    const int SMEM_DYN = 4 * TILE_B;   // 73728 bytes: 2 stages x (A + B)
    static bool attr_set = false;
    if (!attr_set) {
        cudaFuncSetAttribute(mma_gemm_kernel<1>, cudaFuncAttributeMaxDynamicSharedMemorySize, SMEM_DYN);
        cudaFuncSetAttribute(mma_gemm_kernel<2>, cudaFuncAttributeMaxDynamicSharedMemorySize, SMEM_DYN);
        attr_set = true;
    }

    detect_zero_kernel<<<(N_NODES + 255) / 256, 256>>>((const int*)ei);
    count_kernel<<<(N_EDGES + 255) / 256, 256>>>(ei);
    packW_kernel<<<(HID * 112 + N2 * HID + 255) / 256, 256>>>(W1l, W1r, W2l, W2r);
    scan_kernel<<<1, 1024>>>();
    bucket_kernel<<<(N_EDGES + 255) / 256, 256>>>(ei);
    aggx_pack_kernel<<<(N_NODES * 32 + 255) / 256, 256>>>(x);
    mma_gemm_kernel<1><<<dim3(HID / 128, M_PAD / 128), 256, SMEM_DYN>>>(b1);
    mma_gemm_kernel<2><<<dim3(N2 / 128, M_PAD / 128), 256, SMEM_DYN>>>(nullptr);
    final_kernel<<<(N_NODES + 7) / 8, 256>>>(b2, out);
}

// round 8
// speedup vs baseline: 2.6734x; 1.2203x over previous
#include <cuda_runtime.h>
#include <cuda_bf16.h>
#include <cstdint>

#define N_NODES 10000
#define M_PAD   10112     // 79 tiles of 128
#define N_EDGES 160000
#define F0      50
#define HID     512
#define F2      121
#define N2      256
// layer 1: logical K' = 3*128 = 384 (panel width 128, data 112 used)
//   A stored 2 panels [hi|lo] = 256 cols ; B stored 3 panels [hi|lo|hi] = 384
// layer 2: logical K' = 3*512 = 1536
//   A stored 2 panels [hi|lo] = 1024 cols ; B stored 3 panels [hi|lo|hi] = 1536
#define KA1     256
#define KB1     384
#define KA2     1024
#define KB2     1536

// ---------------- scratch (device globals; zero-initialized) -----------------
__device__ int   g_is64;
__device__ int   g_deg[N_NODES];
__device__ int   g_rowstart[N_NODES];
__device__ int   g_cursor[N_NODES];
__device__ float g_invdeg[N_NODES];
__device__ int   g_esrc[N_EDGES];
__device__ __align__(16) __nv_bfloat16 g_a1[(size_t)M_PAD * KA1];
__device__ __align__(16) __nv_bfloat16 g_b1p[(size_t)HID * KB1];
__device__ __align__(16) __nv_bfloat16 g_a2[(size_t)M_PAD * KA2];
__device__ __align__(16) __nv_bfloat16 g_b2p[(size_t)N2 * KB2];
__device__ __align__(16) float g_qr[(size_t)M_PAD * N2];            // [q | r | pad]

// ---------------- PTX helpers -------------------------------------------------
__device__ __forceinline__ uint32_t smem_u32(const void* p) {
    uint32_t a;
    asm("{ .reg .u64 t; cvta.to.shared.u64 t, %1; cvt.u32.u64 %0, t; }" : "=r"(a) : "l"(p));
    return a;
}
#define CP16(dst, src) \
    asm volatile("cp.async.cg.shared.global [%0], [%1], 16;" :: "r"(dst), "l"(src) : "memory")
#define CP_COMMIT() asm volatile("cp.async.commit_group;" ::: "memory")
#define CP_WAIT(n)  asm volatile("cp.async.wait_group %0;" :: "n"(n) : "memory")
#define LDSM_X4(r0, r1, r2, r3, addr) \
    asm volatile("ldmatrix.sync.aligned.m8n8.x4.shared.b16 {%0,%1,%2,%3}, [%4];" \
                 : "=r"(r0), "=r"(r1), "=r"(r2), "=r"(r3) : "r"(addr))
#define LDSM_X2(r0, r1, addr) \
    asm volatile("ldmatrix.sync.aligned.m8n8.x2.shared.b16 {%0,%1}, [%2];" \
                 : "=r"(r0), "=r"(r1) : "r"(addr))

__device__ __forceinline__ void mma16816(float* d, const uint32_t* a, const uint32_t* b) {
    asm volatile(
        "mma.sync.aligned.m16n8k16.row.col.f32.bf16.bf16.f32 "
        "{%0,%1,%2,%3}, {%4,%5,%6,%7}, {%8,%9}, {%0,%1,%2,%3};"
        : "+f"(d[0]), "+f"(d[1]), "+f"(d[2]), "+f"(d[3])
        : "r"(a[0]), "r"(a[1]), "r"(a[2]), "r"(a[3]), "r"(b[0]), "r"(b[1]));
}

// ---------------- edge-index dtype detection + deg zero ----------------------
// int64 with values < 2^31: every odd int32 word is 0. Check 128 odd words in
// parallel with warp 0 of block 0.
__global__ void detect_zero_kernel(const int* __restrict__ ei32) {
    int i = blockIdx.x * blockDim.x + threadIdx.x;
    if (i < N_NODES) g_deg[i] = 0;
    if (blockIdx.x == 0 && threadIdx.x < 32) {
        int lane = threadIdx.x;
        int nz = 0;
#pragma unroll
        for (int r = 0; r < 4; r++) nz |= (ei32[1 + 2 * (lane + r * 32)] != 0);
        unsigned any = __ballot_sync(0xFFFFFFFFu, nz);
        if (lane == 0) g_is64 = any ? 0 : 1;
    }
}
__device__ __forceinline__ int load_idx(const void* ei, int pos) {
    int v = g_is64 ? (int)((const long long*)ei)[pos] : ((const int*)ei)[pos];
    return min(max(v, 0), N_NODES - 1);
}

// ---------------- CSR build --------------------------------------------------
__global__ void count_kernel(const void* __restrict__ ei) {
    int e = blockIdx.x * blockDim.x + threadIdx.x;
    if (e < N_EDGES) atomicAdd(&g_deg[load_idx(ei, N_EDGES + e)], 1);
}

// Two-level shfl scan: 1024 threads x 10 elems, 2 barriers total.
__global__ void scan_kernel() {
    const int CH = 10;
    __shared__ int s_w[32];
    int t = threadIdx.x, lane = t & 31, wid = t >> 5;
    int base = t * CH;
    int local[CH];
    int sum = 0;
#pragma unroll
    for (int i = 0; i < CH; i++) {
        int idx = base + i;
        int v = (idx < N_NODES) ? g_deg[idx] : 0;
        local[i] = v; sum += v;
    }
    // warp-inclusive scan of per-thread sums
    int incl = sum;
#pragma unroll
    for (int off = 1; off < 32; off <<= 1) {
        int v = __shfl_up_sync(0xFFFFFFFFu, incl, off);
        if (lane >= off) incl += v;
    }
    if (lane == 31) s_w[wid] = incl;
    __syncthreads();
    if (wid == 0) {
        int v = s_w[lane];
        int wi = v;
#pragma unroll
        for (int off = 1; off < 32; off <<= 1) {
            int u = __shfl_up_sync(0xFFFFFFFFu, wi, off);
            if (lane >= off) wi += u;
        }
        s_w[lane] = wi - v;   // exclusive warp base
    }
    __syncthreads();
    int excl = s_w[wid] + (incl - sum);
#pragma unroll
    for (int i = 0; i < CH; i++) {
        int idx = base + i;
        if (idx < N_NODES) {
            g_rowstart[idx] = excl; g_cursor[idx] = excl;
            int d = local[i];
            g_invdeg[idx] = 1.0f / (float)(d > 1 ? d : 1);
            excl += d;
        }
    }
}
__global__ void bucket_kernel(const void* __restrict__ ei) {
    int e = blockIdx.x * blockDim.x + threadIdx.x;
    if (e < N_EDGES) {
        int dst = load_idx(ei, N_EDGES + e);
        int pos = atomicAdd(&g_cursor[dst], 1);
        pos = min(max(pos, 0), N_EDGES - 1);
        g_esrc[pos] = load_idx(ei, e);
    }
}

// ---------------- hi/lo helpers ----------------------------------------------
__device__ __forceinline__ void hilo(float v, __nv_bfloat16& h, __nv_bfloat16& l) {
    h = __float2bfloat16_rn(v);
    l = __float2bfloat16_rn(v - __bfloat162float(h));
}

// ---------------- layer-1 aggregation + A1 pack (2 panels: hi | lo) ----------
__global__ void aggx_pack_kernel(const float* __restrict__ x) {
    int gw = (blockIdx.x * blockDim.x + threadIdx.x) >> 5;
    int lane = threadIdx.x & 31;
    if (gw >= N_NODES) return;
    int beg = g_rowstart[gw], d = g_deg[gw];
    float s0 = 0.f, s1 = 0.f;
    for (int i = 0; i < d; i++) {
        int s = g_esrc[beg + i];
        const float* xr = x + s * F0;
        s0 += xr[lane];
        if (lane < F0 - 32) s1 += xr[lane + 32];
    }
    float inv = g_invdeg[gw];
    const float* xs = x + gw * F0;
    size_t rb = (size_t)gw * KA1;
    __nv_bfloat16 h, l;
#define WR_A1(j, v) do { hilo((v), h, l); g_a1[rb + (j)] = h; g_a1[rb + 128 + (j)] = l; } while (0)
    WR_A1(lane, s0 * inv);
    if (lane < F0 - 32) WR_A1(lane + 32, s1 * inv);
    WR_A1(F0 + lane, xs[lane]);
    if (lane < F0 - 32) WR_A1(F0 + lane + 32, xs[lane + 32]);
#undef WR_A1
}

// ---------------- weight packs (merged) --------------------------------------
__global__ void packW_kernel(const float* __restrict__ W1l, const float* __restrict__ W1r,
                             const float* __restrict__ W2l, const float* __restrict__ W2r) {
    int idx = blockIdx.x * blockDim.x + threadIdx.x;
    if (idx < HID * 112) {
        int k = idx % 112, n = idx / 112;
        float v = 0.f;
        if (k < F0)            v = W1l[k * HID + n];
        else if (k < 2 * F0)   v = W1r[(k - F0) * HID + n];
        __nv_bfloat16 h, l; hilo(v, h, l);
        size_t rb = (size_t)n * KB1;
        g_b1p[rb + k] = h; g_b1p[rb + 128 + k] = l; g_b1p[rb + 256 + k] = h;
    } else {
        int i2 = idx - HID * 112;
        if (i2 >= N2 * HID) return;
        int k = i2 % HID, n = i2 / HID;
        float v = 0.f;
        if (n < F2)            v = W2l[k * F2 + n];
        else if (n < 2 * F2)   v = W2r[k * F2 + (n - F2)];
        __nv_bfloat16 h, l; hilo(v, h, l);
        size_t rb = (size_t)n * KB2;
        g_b2p[rb + k] = h; g_b2p[rb + 512 + k] = l; g_b2p[rb + 1024 + k] = h;
    }
}

// ---------------- mma.sync GEMM: C[128x128 tile] = A B^T ---------------------
#define BK      64
#define LDPAD   72        // bf16 elems per smem row (64 + 8 pad) = 144B
#define ROWB    (LDPAD * 2)
#define TILE_B  (128 * ROWB)        // 18432 bytes per operand per stage

template <int MODE>
__global__ void __launch_bounds__(256) mma_gemm_kernel(const float* __restrict__ bias) {
    constexpr int C  = (MODE == 1) ? 6 : 24;
    constexpr int KA = (MODE == 1) ? KA1 : KA2;
    constexpr int KB = (MODE == 1) ? KB1 : KB2;
    const __nv_bfloat16* Ag = (MODE == 1) ? g_a1 : g_a2;
    const __nv_bfloat16* Bg = (MODE == 1) ? g_b1p : g_b2p;

    extern __shared__ __align__(16) char dsm[];
    uint32_t sb = smem_u32(dsm);

    int tid = threadIdx.x, wid = tid >> 5, lane = tid & 31;
    int wm = wid & 1, wn = wid >> 1;       // warp grid 2 (M) x 4 (N)
    int mbase = blockIdx.y * 128, nbase = blockIdx.x * 128;

    float acc[4][4][4];
#pragma unroll
    for (int i = 0; i < 4; i++)
#pragma unroll
        for (int j = 0; j < 4; j++)
#pragma unroll
            for (int k = 0; k < 4; k++) acc[i][j][k] = 0.f;

    uint32_t a_off[4], b_off[4];
#pragma unroll
    for (int mi = 0; mi < 4; mi++)
        a_off[mi] = (uint32_t)(wm * 64 + mi * 16 + (lane & 15)) * ROWB + (uint32_t)(lane >> 4) * 16u;
#pragma unroll
    for (int ni = 0; ni < 4; ni++)
        b_off[ni] = (uint32_t)(wn * 32 + ni * 8 + (lane & 7)) * ROWB + (uint32_t)((lane >> 3) & 1) * 16u;

    auto aoff_of = [](int c) -> int {
        if (MODE == 1) {
            const int m[6] = {0, 64, 0, 64, 128, 192};
            return m[c];
        } else {
            return (c < 16) ? (c & 7) * 64 : 512 + (c - 16) * 64;
        }
    };

    auto load_chunk = [&](int c, int s) {
        uint32_t da = sb + s * 2 * TILE_B;
        uint32_t db = da + TILE_B;
        const __nv_bfloat16* asrc = Ag + (size_t)mbase * KA + aoff_of(c);
        const __nv_bfloat16* bsrc = Bg + (size_t)nbase * KB + c * BK;
#pragma unroll
        for (int i = 0; i < 4; i++) {
            int seg = tid + i * 256;          // 0..1023
            int row = seg >> 3, s16 = seg & 7;
            uint32_t off = row * ROWB + s16 * 16;
            CP16(da + off, asrc + (size_t)row * KA + s16 * 8);
            CP16(db + off, bsrc + (size_t)row * KB + s16 * 8);
        }
        CP_COMMIT();
    };

    load_chunk(0, 0);

    for (int c = 0; c < C; ++c) {
        int s = c & 1;
        if (c + 1 < C) { load_chunk(c + 1, s ^ 1); CP_WAIT(1); }
        else           { CP_WAIT(0); }
        __syncthreads();

        uint32_t As = sb + s * 2 * TILE_B;
        uint32_t Bs = As + TILE_B;
#pragma unroll
        for (int k16 = 0; k16 < BK / 16; ++k16) {
            uint32_t afr[4][4], bfr[4][2];
#pragma unroll
            for (int mi = 0; mi < 4; mi++)
                LDSM_X4(afr[mi][0], afr[mi][1], afr[mi][2], afr[mi][3],
                        As + a_off[mi] + k16 * 32u);
#pragma unroll
            for (int ni = 0; ni < 4; ni++)
                LDSM_X2(bfr[ni][0], bfr[ni][1], Bs + b_off[ni] + k16 * 32u);
#pragma unroll
            for (int mi = 0; mi < 4; mi++)
#pragma unroll
                for (int ni = 0; ni < 4; ni++)
                    mma16816(acc[mi][ni], afr[mi], bfr[ni]);
        }
        __syncthreads();
    }

    // ---- epilogue ----
    int lr = lane >> 2, lc = lane & 3;
#pragma unroll
    for (int mi = 0; mi < 4; mi++) {
        int row0 = mbase + wm * 64 + mi * 16 + lr;
        int row1 = row0 + 8;
#pragma unroll
        for (int ni = 0; ni < 4; ni++) {
            int col0 = nbase + wn * 32 + ni * 8 + lc * 2;
            float* d = acc[mi][ni];
            if (MODE == 1) {
                float bb0 = bias[col0], bb1 = bias[col0 + 1];
#pragma unroll
                for (int half = 0; half < 2; half++) {
                    int r = half ? row1 : row0;
                    if (r >= N_NODES) continue;
                    float v0 = fmaxf(d[half * 2 + 0] + bb0, 0.f);
                    float v1 = fmaxf(d[half * 2 + 1] + bb1, 0.f);
                    __nv_bfloat16 h0, l0, h1, l1;
                    hilo(v0, h0, l0); hilo(v1, h1, l1);
                    size_t rb = (size_t)r * KA2;
                    __nv_bfloat162 hp; hp.x = h0; hp.y = h1;
                    __nv_bfloat162 lp; lp.x = l0; lp.y = l1;
                    *reinterpret_cast<__nv_bfloat162*>(&g_a2[rb + col0]) = hp;
                    *reinterpret_cast<__nv_bfloat162*>(&g_a2[rb + 512 + col0]) = lp;
                }
            } else {
                if (row0 < N_NODES)
                    *reinterpret_cast<float2*>(&g_qr[(size_t)row0 * N2 + col0]) =
                        make_float2(d[0], d[1]);
                if (row1 < N_NODES)
                    *reinterpret_cast<float2*>(&g_qr[(size_t)row1 * N2 + col0]) =
                        make_float2(d[2], d[3]);
            }
        }
    }
}

// ---------------- final: out = mean_agg(q) + r + b2 --------------------------
__global__ void final_kernel(const float* __restrict__ b2, float* __restrict__ out) {
    int gw = (blockIdx.x * blockDim.x + threadIdx.x) >> 5;
    int lane = threadIdx.x & 31;
    if (gw >= N_NODES) return;
    int beg = g_rowstart[gw], d = g_deg[gw];
    int j4 = lane * 4;
    float4 acc = make_float4(0.f, 0.f, 0.f, 0.f);
    for (int i = 0; i < d; i++) {
        int s = g_esrc[beg + i];
        float4 v = *reinterpret_cast<const float4*>(g_qr + (size_t)s * N2 + j4);
        acc.x += v.x; acc.y += v.y; acc.z += v.z; acc.w += v.w;
    }
    float inv = g_invdeg[gw];
    const float* rrow = g_qr + (size_t)gw * N2 + F2;
    float* orow = out + (size_t)gw * F2;
    float av[4] = {acc.x, acc.y, acc.z, acc.w};
#pragma unroll
    for (int c = 0; c < 4; c++) {
        int jj = j4 + c;
        if (jj < F2) orow[jj] = av[c] * inv + rrow[jj] + b2[jj];
    }
}

// ---------------- launch ------------------------------------------------------
extern "C" void kernel_launch(void* const* d_in, const int* in_sizes, int n_in,
                              void* d_out, int out_size) {
    const float* x   = (const float*)d_in[0];
    const void*  ei  = d_in[1];
    const float* W1l = (const float*)d_in[2];
    const float* W1r = (const float*)d_in[3];
    const float* b1  = (const float*)d_in[4];
    const float* W2l = (const float*)d_in[5];
    const float* W2r = (const float*)d_in[6];
    const float* b2  = (const float*)d_in[7];
    float*       out = (float*)d_out;

    const int SMEM_DYN = 4 * TILE_B;   // 73728 bytes: 2 stages x (A + B)
    static bool attr_set = false;
    if (!attr_set) {
        cudaFuncSetAttribute(mma_gemm_kernel<1>, cudaFuncAttributeMaxDynamicSharedMemorySize, SMEM_DYN);
        cudaFuncSetAttribute(mma_gemm_kernel<2>, cudaFuncAttributeMaxDynamicSharedMemorySize, SMEM_DYN);
        attr_set = true;
    }

    detect_zero_kernel<<<(N_NODES + 255) / 256, 256>>>((const int*)ei);
    count_kernel<<<(N_EDGES + 255) / 256, 256>>>(ei);
    packW_kernel<<<(HID * 112 + N2 * HID + 255) / 256, 256>>>(W1l, W1r, W2l, W2r);
    scan_kernel<<<1, 1024>>>();
    bucket_kernel<<<(N_EDGES + 255) / 256, 256>>>(ei);
    aggx_pack_kernel<<<(N_NODES * 32 + 255) / 256, 256>>>(x);
    mma_gemm_kernel<1><<<dim3(HID / 128, M_PAD / 128), 256, SMEM_DYN>>>(b1);
    mma_gemm_kernel<2><<<dim3(N2 / 128, M_PAD / 128), 256, SMEM_DYN>>>(nullptr);
    final_kernel<<<(N_NODES + 7) / 8, 256>>>(b2, out);
}

// round 9
// speedup vs baseline: 2.9788x; 1.1142x over previous
#include <cuda_runtime.h>
#include <cuda_bf16.h>
#include <cstdint>

#define N_NODES 10000
#define M_PAD   10112     // 79 tiles of 128
#define N_EDGES 160000
#define F0      50
#define HID     512
#define F2      121
#define N2      256
#define KA1     256
#define KB1     384
#define KA2     1024
#define KB2     1536

// ---------------- scratch (device globals; zero-initialized) -----------------
__device__ int   g_is64;
__device__ __align__(16) int   g_deg[N_NODES + 16];
__device__ __align__(16) int   g_rowstart[N_NODES + 16];
__device__ __align__(16) int   g_cursor[N_NODES + 16];
__device__ __align__(16) float g_invdeg[N_NODES + 16];
__device__ int   g_esrc[N_EDGES];
__device__ __align__(16) __nv_bfloat16 g_a1[(size_t)M_PAD * KA1];
__device__ __align__(16) __nv_bfloat16 g_b1p[(size_t)HID * KB1];
__device__ __align__(16) __nv_bfloat16 g_a2[(size_t)M_PAD * KA2];
__device__ __align__(16) __nv_bfloat16 g_b2p[(size_t)N2 * KB2];
__device__ __align__(16) float g_qr[(size_t)M_PAD * N2];            // [q | r | pad]

// ---------------- PTX helpers -------------------------------------------------
__device__ __forceinline__ uint32_t smem_u32(const void* p) {
    uint32_t a;
    asm("{ .reg .u64 t; cvta.to.shared.u64 t, %1; cvt.u32.u64 %0, t; }" : "=r"(a) : "l"(p));
    return a;
}
#define CP16(dst, src) \
    asm volatile("cp.async.cg.shared.global [%0], [%1], 16;" :: "r"(dst), "l"(src) : "memory")
#define CP_COMMIT() asm volatile("cp.async.commit_group;" ::: "memory")
#define CP_WAIT(n)  asm volatile("cp.async.wait_group %0;" :: "n"(n) : "memory")
#define LDSM_X4(r0, r1, r2, r3, addr) \
    asm volatile("ldmatrix.sync.aligned.m8n8.x4.shared.b16 {%0,%1,%2,%3}, [%4];" \
                 : "=r"(r0), "=r"(r1), "=r"(r2), "=r"(r3) : "r"(addr))
#define LDSM_X2(r0, r1, addr) \
    asm volatile("ldmatrix.sync.aligned.m8n8.x2.shared.b16 {%0,%1}, [%2];" \
                 : "=r"(r0), "=r"(r1) : "r"(addr))

__device__ __forceinline__ void mma16816(float* d, const uint32_t* a, const uint32_t* b) {
    asm volatile(
        "mma.sync.aligned.m16n8k16.row.col.f32.bf16.bf16.f32 "
        "{%0,%1,%2,%3}, {%4,%5,%6,%7}, {%8,%9}, {%0,%1,%2,%3};"
        : "+f"(d[0]), "+f"(d[1]), "+f"(d[2]), "+f"(d[3])
        : "r"(a[0]), "r"(a[1]), "r"(a[2]), "r"(a[3]), "r"(b[0]), "r"(b[1]));
}

// ---------------- hi/lo helpers ----------------------------------------------
__device__ __forceinline__ void hilo(float v, __nv_bfloat16& h, __nv_bfloat16& l) {
    h = __float2bfloat16_rn(v);
    l = __float2bfloat16_rn(v - __bfloat162float(h));
}

// ---------------- prep: zero deg + dtype detect + weight packs ---------------
__global__ void prep_kernel(const int* __restrict__ ei32,
                            const float* __restrict__ W1l, const float* __restrict__ W1r,
                            const float* __restrict__ W2l, const float* __restrict__ W2r) {
    int idx = blockIdx.x * blockDim.x + threadIdx.x;
    if (idx < N_NODES) g_deg[idx] = 0;
    if (blockIdx.x == 0 && threadIdx.x < 32) {
        int lane = threadIdx.x;
        int nz = 0;
#pragma unroll
        for (int r = 0; r < 4; r++) nz |= (ei32[1 + 2 * (lane + r * 32)] != 0);
        unsigned any = __ballot_sync(0xFFFFFFFFu, nz);
        if (lane == 0) g_is64 = any ? 0 : 1;
    }
    // weight packs
    if (idx < HID * 112) {
        int k = idx % 112, n = idx / 112;
        float v = 0.f;
        if (k < F0)            v = W1l[k * HID + n];
        else if (k < 2 * F0)   v = W1r[(k - F0) * HID + n];
        __nv_bfloat16 h, l; hilo(v, h, l);
        size_t rb = (size_t)n * KB1;
        g_b1p[rb + k] = h; g_b1p[rb + 128 + k] = l; g_b1p[rb + 256 + k] = h;
    } else {
        int i2 = idx - HID * 112;
        if (i2 < N2 * HID) {
            int k = i2 % HID, n = i2 / HID;
            float v = 0.f;
            if (n < F2)            v = W2l[k * F2 + n];
            else if (n < 2 * F2)   v = W2r[k * F2 + (n - F2)];
            __nv_bfloat16 h, l; hilo(v, h, l);
            size_t rb = (size_t)n * KB2;
            g_b2p[rb + k] = h; g_b2p[rb + 512 + k] = l; g_b2p[rb + 1024 + k] = h;
        }
    }
}

__device__ __forceinline__ int load_idx(const void* ei, int pos) {
    int v = g_is64 ? (int)((const long long*)ei)[pos] : ((const int*)ei)[pos];
    return min(max(v, 0), N_NODES - 1);
}

// ---------------- CSR build --------------------------------------------------
__global__ void count_kernel(const void* __restrict__ ei) {
    int e = blockIdx.x * blockDim.x + threadIdx.x;
    if (e < N_EDGES) atomicAdd(&g_deg[load_idx(ei, N_EDGES + e)], 1);
}

// Vectorized two-level shfl scan: 640 threads x 16 elems (int4), 3 barriers.
__global__ void scan_kernel() {
    const int CH = 16;
    __shared__ int s_w[32];
    int t = threadIdx.x, lane = t & 31, wid = t >> 5;
    int base = t * CH;                       // 64B aligned
    int local[CH];
    int sum = 0;
    if (base < N_NODES) {                    // 625*16 = 10000 exact
#pragma unroll
        for (int v4 = 0; v4 < 4; v4++) {
            int4 v = *reinterpret_cast<const int4*>(&g_deg[base + v4 * 4]);
            local[v4 * 4 + 0] = v.x; local[v4 * 4 + 1] = v.y;
            local[v4 * 4 + 2] = v.z; local[v4 * 4 + 3] = v.w;
            sum += v.x + v.y + v.z + v.w;
        }
    } else {
#pragma unroll
        for (int i = 0; i < CH; i++) local[i] = 0;
    }
    if (t < 32) s_w[t] = 0;
    __syncthreads();
    int incl = sum;
#pragma unroll
    for (int off = 1; off < 32; off <<= 1) {
        int v = __shfl_up_sync(0xFFFFFFFFu, incl, off);
        if (lane >= off) incl += v;
    }
    if (lane == 31) s_w[wid] = incl;
    __syncthreads();
    if (wid == 0) {
        int v = s_w[lane];
        int wi = v;
#pragma unroll
        for (int off = 1; off < 32; off <<= 1) {
            int u = __shfl_up_sync(0xFFFFFFFFu, wi, off);
            if (lane >= off) wi += u;
        }
        s_w[lane] = wi - v;   // exclusive warp base
    }
    __syncthreads();
    if (base >= N_NODES) return;
    int excl = s_w[wid] + (incl - sum);
#pragma unroll
    for (int v4 = 0; v4 < 4; v4++) {
        int4 rs; float4 iv;
        int d0 = local[v4 * 4 + 0], d1 = local[v4 * 4 + 1];
        int d2 = local[v4 * 4 + 2], d3 = local[v4 * 4 + 3];
        rs.x = excl;            rs.y = excl + d0;
        rs.z = excl + d0 + d1;  rs.w = excl + d0 + d1 + d2;
        excl += d0 + d1 + d2 + d3;
        iv.x = 1.0f / (float)(d0 > 1 ? d0 : 1);
        iv.y = 1.0f / (float)(d1 > 1 ? d1 : 1);
        iv.z = 1.0f / (float)(d2 > 1 ? d2 : 1);
        iv.w = 1.0f / (float)(d3 > 1 ? d3 : 1);
        *reinterpret_cast<int4*>(&g_rowstart[base + v4 * 4]) = rs;
        *reinterpret_cast<int4*>(&g_cursor[base + v4 * 4])   = rs;
        *reinterpret_cast<float4*>(&g_invdeg[base + v4 * 4]) = iv;
    }
}

__global__ void bucket_kernel(const void* __restrict__ ei) {
    int e = blockIdx.x * blockDim.x + threadIdx.x;
    if (e < N_EDGES) {
        int dst = load_idx(ei, N_EDGES + e);
        int pos = atomicAdd(&g_cursor[dst], 1);
        pos = min(max(pos, 0), N_EDGES - 1);
        g_esrc[pos] = load_idx(ei, e);
    }
}

// ---------------- layer-1 aggregation + A1 pack (2 panels: hi | lo) ----------
__global__ void aggx_pack_kernel(const float* __restrict__ x) {
    int gw = (blockIdx.x * blockDim.x + threadIdx.x) >> 5;
    int lane = threadIdx.x & 31;
    if (gw >= N_NODES) return;
    int beg = g_rowstart[gw], d = g_deg[gw];
    float s0 = 0.f, s1 = 0.f;
    int i = 0;
    for (; i + 2 <= d; i += 2) {
        int sa = g_esrc[beg + i], sb = g_esrc[beg + i + 1];
        const float* xa = x + sa * F0;
        const float* xb = x + sb * F0;
        s0 += xa[lane] + xb[lane];
        if (lane < F0 - 32) s1 += xa[lane + 32] + xb[lane + 32];
    }
    if (i < d) {
        const float* xa = x + g_esrc[beg + i] * F0;
        s0 += xa[lane];
        if (lane < F0 - 32) s1 += xa[lane + 32];
    }
    float inv = g_invdeg[gw];
    const float* xs = x + gw * F0;
    size_t rb = (size_t)gw * KA1;
    __nv_bfloat16 h, l;
#define WR_A1(j, v) do { hilo((v), h, l); g_a1[rb + (j)] = h; g_a1[rb + 128 + (j)] = l; } while (0)
    WR_A1(lane, s0 * inv);
    if (lane < F0 - 32) WR_A1(lane + 32, s1 * inv);
    WR_A1(F0 + lane, xs[lane]);
    if (lane < F0 - 32) WR_A1(F0 + lane + 32, xs[lane + 32]);
#undef WR_A1
}

// ---------------- mma.sync GEMM: C[128x128 tile] = A B^T ---------------------
#define BK      64
#define LDPAD   72        // bf16 elems per smem row (64 + 8 pad) = 144B
#define ROWB    (LDPAD * 2)
#define TILE_B  (128 * ROWB)        // 18432 bytes per operand per stage

template <int MODE>
__global__ void __launch_bounds__(256) mma_gemm_kernel(const float* __restrict__ bias) {
    constexpr int C  = (MODE == 1) ? 6 : 24;
    constexpr int KA = (MODE == 1) ? KA1 : KA2;
    constexpr int KB = (MODE == 1) ? KB1 : KB2;
    const __nv_bfloat16* Ag = (MODE == 1) ? g_a1 : g_a2;
    const __nv_bfloat16* Bg = (MODE == 1) ? g_b1p : g_b2p;

    extern __shared__ __align__(16) char dsm[];
    uint32_t sb = smem_u32(dsm);

    int tid = threadIdx.x, wid = tid >> 5, lane = tid & 31;
    int wm = wid & 1, wn = wid >> 1;       // warp grid 2 (M) x 4 (N)
    int mbase = blockIdx.y * 128, nbase = blockIdx.x * 128;

    float acc[4][4][4];
#pragma unroll
    for (int i = 0; i < 4; i++)
#pragma unroll
        for (int j = 0; j < 4; j++)
#pragma unroll
            for (int k = 0; k < 4; k++) acc[i][j][k] = 0.f;

    uint32_t a_off[4], b_off[4];
#pragma unroll
    for (int mi = 0; mi < 4; mi++)
        a_off[mi] = (uint32_t)(wm * 64 + mi * 16 + (lane & 15)) * ROWB + (uint32_t)(lane >> 4) * 16u;
#pragma unroll
    for (int ni = 0; ni < 4; ni++)
        b_off[ni] = (uint32_t)(wn * 32 + ni * 8 + (lane & 7)) * ROWB + (uint32_t)((lane >> 3) & 1) * 16u;

    auto aoff_of = [](int c) -> int {
        if (MODE == 1) {
            const int m[6] = {0, 64, 0, 64, 128, 192};
            return m[c];
        } else {
            return (c < 16) ? (c & 7) * 64 : 512 + (c - 16) * 64;
        }
    };

    auto load_chunk = [&](int c, int s) {
        uint32_t da = sb + s * 2 * TILE_B;
        uint32_t db = da + TILE_B;
        const __nv_bfloat16* asrc = Ag + (size_t)mbase * KA + aoff_of(c);
        const __nv_bfloat16* bsrc = Bg + (size_t)nbase * KB + c * BK;
#pragma unroll
        for (int i = 0; i < 4; i++) {
            int seg = tid + i * 256;          // 0..1023
            int row = seg >> 3, s16 = seg & 7;
            uint32_t off = row * ROWB + s16 * 16;
            CP16(da + off, asrc + (size_t)row * KA + s16 * 8);
            CP16(db + off, bsrc + (size_t)row * KB + s16 * 8);
        }
        CP_COMMIT();
    };

    load_chunk(0, 0);

    for (int c = 0; c < C; ++c) {
        int s = c & 1;
        if (c + 1 < C) { load_chunk(c + 1, s ^ 1); CP_WAIT(1); }
        else           { CP_WAIT(0); }
        __syncthreads();

        uint32_t As = sb + s * 2 * TILE_B;
        uint32_t Bs = As + TILE_B;
#pragma unroll
        for (int k16 = 0; k16 < BK / 16; ++k16) {
            uint32_t afr[4][4], bfr[4][2];
#pragma unroll
            for (int mi = 0; mi < 4; mi++)
                LDSM_X4(afr[mi][0], afr[mi][1], afr[mi][2], afr[mi][3],
                        As + a_off[mi] + k16 * 32u);
#pragma unroll
            for (int ni = 0; ni < 4; ni++)
                LDSM_X2(bfr[ni][0], bfr[ni][1], Bs + b_off[ni] + k16 * 32u);
#pragma unroll
            for (int mi = 0; mi < 4; mi++)
#pragma unroll
                for (int ni = 0; ni < 4; ni++)
                    mma16816(acc[mi][ni], afr[mi], bfr[ni]);
        }
        __syncthreads();
    }

    // ---- epilogue ----
    int lr = lane >> 2, lc = lane & 3;
#pragma unroll
    for (int mi = 0; mi < 4; mi++) {
        int row0 = mbase + wm * 64 + mi * 16 + lr;
        int row1 = row0 + 8;
#pragma unroll
        for (int ni = 0; ni < 4; ni++) {
            int col0 = nbase + wn * 32 + ni * 8 + lc * 2;
            float* d = acc[mi][ni];
            if (MODE == 1) {
                float bb0 = bias[col0], bb1 = bias[col0 + 1];
#pragma unroll
                for (int half = 0; half < 2; half++) {
                    int r = half ? row1 : row0;
                    if (r >= N_NODES) continue;
                    float v0 = fmaxf(d[half * 2 + 0] + bb0, 0.f);
                    float v1 = fmaxf(d[half * 2 + 1] + bb1, 0.f);
                    __nv_bfloat16 h0, l0, h1, l1;
                    hilo(v0, h0, l0); hilo(v1, h1, l1);
                    size_t rb = (size_t)r * KA2;
                    __nv_bfloat162 hp; hp.x = h0; hp.y = h1;
                    __nv_bfloat162 lp; lp.x = l0; lp.y = l1;
                    *reinterpret_cast<__nv_bfloat162*>(&g_a2[rb + col0]) = hp;
                    *reinterpret_cast<__nv_bfloat162*>(&g_a2[rb + 512 + col0]) = lp;
                }
            } else {
                if (row0 < N_NODES)
                    *reinterpret_cast<float2*>(&g_qr[(size_t)row0 * N2 + col0]) =
                        make_float2(d[0], d[1]);
                if (row1 < N_NODES)
                    *reinterpret_cast<float2*>(&g_qr[(size_t)row1 * N2 + col0]) =
                        make_float2(d[2], d[3]);
            }
        }
    }
}

// ---------------- final: out = mean_agg(q) + r + b2 --------------------------
__global__ void final_kernel(const float* __restrict__ b2, float* __restrict__ out) {
    int gw = (blockIdx.x * blockDim.x + threadIdx.x) >> 5;
    int lane = threadIdx.x & 31;
    if (gw >= N_NODES) return;
    int beg = g_rowstart[gw], d = g_deg[gw];
    int j4 = lane * 4;
    float4 acc = make_float4(0.f, 0.f, 0.f, 0.f);
    int i = 0;
    for (; i + 2 <= d; i += 2) {
        int sa = g_esrc[beg + i], sb = g_esrc[beg + i + 1];
        float4 va = *reinterpret_cast<const float4*>(g_qr + (size_t)sa * N2 + j4);
        float4 vb = *reinterpret_cast<const float4*>(g_qr + (size_t)sb * N2 + j4);
        acc.x += va.x + vb.x; acc.y += va.y + vb.y;
        acc.z += va.z + vb.z; acc.w += va.w + vb.w;
    }
    if (i < d) {
        int sa = g_esrc[beg + i];
        float4 va = *reinterpret_cast<const float4*>(g_qr + (size_t)sa * N2 + j4);
        acc.x += va.x; acc.y += va.y; acc.z += va.z; acc.w += va.w;
    }
    float inv = g_invdeg[gw];
    const float* rrow = g_qr + (size_t)gw * N2 + F2;
    float* orow = out + (size_t)gw * F2;
    float av[4] = {acc.x, acc.y, acc.z, acc.w};
#pragma unroll
    for (int c = 0; c < 4; c++) {
        int jj = j4 + c;
        if (jj < F2) orow[jj] = av[c] * inv + rrow[jj] + b2[jj];
    }
}

// ---------------- launch ------------------------------------------------------
extern "C" void kernel_launch(void* const* d_in, const int* in_sizes, int n_in,
                              void* d_out, int out_size) {
    const float* x   = (const float*)d_in[0];
    const void*  ei  = d_in[1];
    const float* W1l = (const float*)d_in[2];
    const float* W1r = (const float*)d_in[3];
    const float* b1  = (const float*)d_in[4];
    const float* W2l = (const float*)d_in[5];
    const float* W2r = (const float*)d_in[6];
    const float* b2  = (const float*)d_in[7];
    float*       out = (float*)d_out;

    const int SMEM_DYN = 4 * TILE_B;   // 73728 bytes: 2 stages x (A + B)
    static bool attr_set = false;
    if (!attr_set) {
        cudaFuncSetAttribute(mma_gemm_kernel<1>, cudaFuncAttributeMaxDynamicSharedMemorySize, SMEM_DYN);
        cudaFuncSetAttribute(mma_gemm_kernel<2>, cudaFuncAttributeMaxDynamicSharedMemorySize, SMEM_DYN);
        attr_set = true;
    }

    const int PREP_ELEMS = HID * 112 + N2 * HID;   // 188416
    prep_kernel<<<(PREP_ELEMS + 255) / 256, 256>>>((const int*)ei, W1l, W1r, W2l, W2r);
    count_kernel<<<(N_EDGES + 255) / 256, 256>>>(ei);
    scan_kernel<<<1, 640>>>();
    bucket_kernel<<<(N_EDGES + 255) / 256, 256>>>(ei);
    aggx_pack_kernel<<<(N_NODES * 32 + 255) / 256, 256>>>(x);
    mma_gemm_kernel<1><<<dim3(HID / 128, M_PAD / 128), 256, SMEM_DYN>>>(b1);
    mma_gemm_kernel<2><<<dim3(N2 / 128, M_PAD / 128), 256, SMEM_DYN>>>(nullptr);
    final_kernel<<<(N_NODES + 7) / 8, 256>>>(b2, out);
}